// round 1
// baseline (speedup 1.0000x reference)
#include <cuda_runtime.h>
#include <math.h>
#include <stdint.h>

// Problem constants
#define BATCH   2
#define NSEQ    2048
#define DMODEL  1024
#define HEADS   16
#define DH      64
#define INNER   1024          // HEADS*DH
#define NROWS   (BATCH*NSEQ)  // 4096
#define SCALE   0.125f        // DH^-0.5
#define LN_EPS  1e-5f

// ---------------------------------------------------------------------------
// Scratch (no allocations allowed -> __device__ globals)
// ---------------------------------------------------------------------------
__device__ float g_xn [(size_t)NROWS * DMODEL];      // 16.8 MB
__device__ float g_qkv[(size_t)NROWS * 3 * INNER];   // 50.3 MB
__device__ float g_ctx[(size_t)NROWS * INNER];       // 16.8 MB

// ---------------------------------------------------------------------------
// Kernel 1: LayerNorm. One block per row, 256 threads, float4 per thread.
// ---------------------------------------------------------------------------
__global__ __launch_bounds__(256) void ln_kernel(
    const float* __restrict__ x, const float* __restrict__ gamma,
    const float* __restrict__ beta, float* __restrict__ xn)
{
    int row = blockIdx.x;
    int tid = threadIdx.x;
    const float4* xr = (const float4*)(x + (size_t)row * DMODEL);
    float4 v = xr[tid];

    float s  = v.x + v.y + v.z + v.w;
    float ss = v.x*v.x + v.y*v.y + v.z*v.z + v.w*v.w;

    #pragma unroll
    for (int off = 16; off; off >>= 1) {
        s  += __shfl_xor_sync(0xffffffffu, s,  off);
        ss += __shfl_xor_sync(0xffffffffu, ss, off);
    }
    __shared__ float sbuf[8], ssbuf[8];
    int warp = tid >> 5, lane = tid & 31;
    if (lane == 0) { sbuf[warp] = s; ssbuf[warp] = ss; }
    __syncthreads();
    s = 0.f; ss = 0.f;
    #pragma unroll
    for (int w = 0; w < 8; w++) { s += sbuf[w]; ss += ssbuf[w]; }

    float mu  = s * (1.0f / DMODEL);
    float var = ss * (1.0f / DMODEL) - mu * mu;
    float inv = rsqrtf(var + LN_EPS);

    float4 g  = ((const float4*)gamma)[tid];
    float4 be = ((const float4*)beta)[tid];
    float4 o;
    o.x = (v.x - mu) * inv * g.x + be.x;
    o.y = (v.y - mu) * inv * g.y + be.y;
    o.z = (v.z - mu) * inv * g.z + be.z;
    o.w = (v.w - mu) * inv * g.w + be.w;
    ((float4*)(xn + (size_t)row * DMODEL))[tid] = o;
}

// ---------------------------------------------------------------------------
// Kernel 2: fp32 SGEMM, C[M,N] = A[M,K] @ B[K,N], all row-major.
// 128x128 tile, BK=8, 256 threads, 8x8 micro-tile, double-buffered smem.
// M,N,K must be multiples of 128/128/8 (true for all uses here).
// ---------------------------------------------------------------------------
__global__ __launch_bounds__(256) void sgemm_kernel(
    const float* __restrict__ A, const float* __restrict__ B,
    float* __restrict__ C, int M, int N, int K)
{
    const int BM = 128, BN = 128, BK = 8;
    __shared__ float As[2][BK][BM];
    __shared__ float Bs[2][BK][BN];

    int tid = threadIdx.x;
    int bx = blockIdx.x, by = blockIdx.y;

    int arow = tid >> 1;            // 0..127
    int acol = (tid & 1) << 2;      // 0 / 4
    int brow = tid >> 5;            // 0..7
    int bcol = (tid & 31) << 2;     // 0..124

    const float* Ag = A + (size_t)(by * BM + arow) * K + acol;
    const float* Bg = B + (size_t)brow * N + (size_t)bx * BN + bcol;

    float4 a4 = *(const float4*)Ag;
    float4 b4 = *(const float4*)Bg;
    As[0][acol + 0][arow] = a4.x;
    As[0][acol + 1][arow] = a4.y;
    As[0][acol + 2][arow] = a4.z;
    As[0][acol + 3][arow] = a4.w;
    *(float4*)&Bs[0][brow][bcol] = b4;
    __syncthreads();

    int tx = (tid & 15) << 3;       // output col offset in tile
    int ty = (tid >> 4) << 3;       // output row offset in tile

    float acc[8][8];
    #pragma unroll
    for (int i = 0; i < 8; i++)
        #pragma unroll
        for (int j = 0; j < 8; j++) acc[i][j] = 0.f;

    int nk = K / BK;
    for (int kt = 0; kt < nk; kt++) {
        int cur = kt & 1;
        if (kt + 1 < nk) {
            a4 = *(const float4*)(Ag + (size_t)(kt + 1) * BK);
            b4 = *(const float4*)(Bg + (size_t)(kt + 1) * BK * N);
        }
        #pragma unroll
        for (int k = 0; k < BK; k++) {
            float4 a0 = *(const float4*)&As[cur][k][ty];
            float4 a1 = *(const float4*)&As[cur][k][ty + 4];
            float4 b0 = *(const float4*)&Bs[cur][k][tx];
            float4 b1 = *(const float4*)&Bs[cur][k][tx + 4];
            float av[8] = {a0.x, a0.y, a0.z, a0.w, a1.x, a1.y, a1.z, a1.w};
            float bv[8] = {b0.x, b0.y, b0.z, b0.w, b1.x, b1.y, b1.z, b1.w};
            #pragma unroll
            for (int i = 0; i < 8; i++)
                #pragma unroll
                for (int j = 0; j < 8; j++)
                    acc[i][j] += av[i] * bv[j];
        }
        if (kt + 1 < nk) {
            int nxt = cur ^ 1;
            As[nxt][acol + 0][arow] = a4.x;
            As[nxt][acol + 1][arow] = a4.y;
            As[nxt][acol + 2][arow] = a4.z;
            As[nxt][acol + 3][arow] = a4.w;
            *(float4*)&Bs[nxt][brow][bcol] = b4;
            __syncthreads();
        }
    }

    float* Cg = C + (size_t)(by * BM + ty) * N + (size_t)bx * BN + tx;
    #pragma unroll
    for (int i = 0; i < 8; i++) {
        float4 c0 = {acc[i][0], acc[i][1], acc[i][2], acc[i][3]};
        float4 c1 = {acc[i][4], acc[i][5], acc[i][6], acc[i][7]};
        *(float4*)(Cg + (size_t)i * N)     = c0;
        *(float4*)(Cg + (size_t)i * N + 4) = c1;
    }
}

// ---------------------------------------------------------------------------
// Kernel 3: flash-style masked attention (fp32).
// grid (NSEQ/64, HEADS, BATCH), 256 threads.
// dots = (Q K^T + m) * SCALE; online softmax; O = P V.
// qkv layout per row: [q(0..1023) | k(1024..2047) | v(2048..3071)],
// head h occupies cols h*64..h*64+63 inside each third.
// ---------------------------------------------------------------------------
#define ATTN_PAD 68
#define ATTN_SMEM (4 * 64 * ATTN_PAD * 4)   // Qt + Kt + Vs + Pt = 69632 B

__global__ __launch_bounds__(256) void attn_kernel(
    const float* __restrict__ qkv, const float* __restrict__ m,
    float* __restrict__ ctx)
{
    extern __shared__ float sm[];
    float (*Qt)[ATTN_PAD] = (float(*)[ATTN_PAD])(sm);                  // [d][qi]
    float (*Kt)[ATTN_PAD] = (float(*)[ATTN_PAD])(sm + 64 * ATTN_PAD);  // [d][kj]
    float (*Vs)[ATTN_PAD] = (float(*)[ATTN_PAD])(sm + 2 * 64 * ATTN_PAD); // [kj][d]
    float (*Pt)[ATTN_PAD] = (float(*)[ATTN_PAD])(sm + 3 * 64 * ATTN_PAD); // [j][qi]

    int tid = threadIdx.x;
    int qt = blockIdx.x, h = blockIdx.y, b = blockIdx.z;
    int q0 = qt * 64;
    size_t rowbase = (size_t)b * NSEQ;

    // Load Q tile transposed: Qt[d][qi]
    {
        int r  = tid >> 2;            // qi 0..63
        int c0 = (tid & 3) << 4;      // d offset 0/16/32/48
        const float* qg = qkv + (rowbase + q0 + r) * (size_t)(3 * INNER) + h * DH + c0;
        #pragma unroll
        for (int l = 0; l < 4; l++) {
            float4 v = *(const float4*)(qg + l * 4);
            int d0 = c0 + l * 4;
            Qt[d0 + 0][r] = v.x; Qt[d0 + 1][r] = v.y;
            Qt[d0 + 2][r] = v.z; Qt[d0 + 3][r] = v.w;
        }
    }

    int tx = tid & 15, ty = tid >> 4;
    int rr = ty * 4;   // local row base (qi)
    int cc = tx * 4;   // local col base (kj for S; d for O)

    float rmax[4], rsum[4], o[4][4];
    #pragma unroll
    for (int i = 0; i < 4; i++) {
        rmax[i] = -1e30f; rsum[i] = 0.f;
        #pragma unroll
        for (int j = 0; j < 4; j++) o[i][j] = 0.f;
    }

    for (int kt = 0; kt < NSEQ / 64; kt++) {
        int k0 = kt * 64;
        // Load K (transposed) and V (straight)
        {
            int r   = tid >> 2;
            int c0l = (tid & 3) << 4;
            const float* kg = qkv + (rowbase + k0 + r) * (size_t)(3 * INNER) + INNER   + h * DH + c0l;
            const float* vg = qkv + (rowbase + k0 + r) * (size_t)(3 * INNER) + 2*INNER + h * DH + c0l;
            #pragma unroll
            for (int l = 0; l < 4; l++) {
                float4 kv = *(const float4*)(kg + l * 4);
                int d0 = c0l + l * 4;
                Kt[d0 + 0][r] = kv.x; Kt[d0 + 1][r] = kv.y;
                Kt[d0 + 2][r] = kv.z; Kt[d0 + 3][r] = kv.w;
                float4 vv = *(const float4*)(vg + l * 4);
                *(float4*)&Vs[r][d0] = vv;
            }
        }
        __syncthreads();

        // S = Q K^T  (4x4 per thread)
        float s[4][4];
        #pragma unroll
        for (int i = 0; i < 4; i++)
            #pragma unroll
            for (int j = 0; j < 4; j++) s[i][j] = 0.f;

        #pragma unroll 8
        for (int k = 0; k < 64; k++) {
            float4 a  = *(const float4*)&Qt[k][rr];
            float4 bb = *(const float4*)&Kt[k][cc];
            float av[4] = {a.x, a.y, a.z, a.w};
            float bv[4] = {bb.x, bb.y, bb.z, bb.w};
            #pragma unroll
            for (int i = 0; i < 4; i++)
                #pragma unroll
                for (int j = 0; j < 4; j++)
                    s[i][j] += av[i] * bv[j];
        }

        // mask before scale (non-standard order per reference)
        const float* mg = m + ((size_t)b * NSEQ + q0 + rr) * NSEQ + k0 + cc;
        #pragma unroll
        for (int i = 0; i < 4; i++) {
            float4 mm = *(const float4*)(mg + (size_t)i * NSEQ);
            s[i][0] = (s[i][0] + mm.x) * SCALE;
            s[i][1] = (s[i][1] + mm.y) * SCALE;
            s[i][2] = (s[i][2] + mm.z) * SCALE;
            s[i][3] = (s[i][3] + mm.w) * SCALE;
        }

        // online softmax across the 16 threads sharing each row
        #pragma unroll
        for (int i = 0; i < 4; i++) {
            float tm = fmaxf(fmaxf(s[i][0], s[i][1]), fmaxf(s[i][2], s[i][3]));
            #pragma unroll
            for (int off = 8; off; off >>= 1)
                tm = fmaxf(tm, __shfl_xor_sync(0xffffffffu, tm, off));
            float nm   = fmaxf(rmax[i], tm);
            float corr = __expf(rmax[i] - nm);
            float ps = 0.f;
            #pragma unroll
            for (int j = 0; j < 4; j++) {
                float p = __expf(s[i][j] - nm);
                s[i][j] = p; ps += p;
            }
            #pragma unroll
            for (int off = 8; off; off >>= 1)
                ps += __shfl_xor_sync(0xffffffffu, ps, off);
            rsum[i] = rsum[i] * corr + ps;
            rmax[i] = nm;
            #pragma unroll
            for (int j = 0; j < 4; j++) o[i][j] *= corr;
        }

        // stage P transposed for the PV gemm
        #pragma unroll
        for (int j = 0; j < 4; j++)
            #pragma unroll
            for (int i = 0; i < 4; i++)
                Pt[cc + j][rr + i] = s[i][j];
        __syncthreads();

        // O += P V
        #pragma unroll 8
        for (int j = 0; j < 64; j++) {
            float4 p  = *(const float4*)&Pt[j][rr];
            float4 vv = *(const float4*)&Vs[j][cc];
            o[0][0] += p.x * vv.x; o[0][1] += p.x * vv.y; o[0][2] += p.x * vv.z; o[0][3] += p.x * vv.w;
            o[1][0] += p.y * vv.x; o[1][1] += p.y * vv.y; o[1][2] += p.y * vv.z; o[1][3] += p.y * vv.w;
            o[2][0] += p.z * vv.x; o[2][1] += p.z * vv.y; o[2][2] += p.z * vv.z; o[2][3] += p.z * vv.w;
            o[3][0] += p.w * vv.x; o[3][1] += p.w * vv.y; o[3][2] += p.w * vv.z; o[3][3] += p.w * vv.w;
        }
        __syncthreads();  // protect Kt/Vs/Pt before next tile's loads
    }

    // normalize and write ctx in [b, n, h*64 + d] layout
    #pragma unroll
    for (int i = 0; i < 4; i++) {
        float inv = 1.0f / rsum[i];
        float4 ov = {o[i][0] * inv, o[i][1] * inv, o[i][2] * inv, o[i][3] * inv};
        float* cg = ctx + (rowbase + q0 + rr + i) * (size_t)INNER + h * DH + cc;
        *(float4*)cg = ov;
    }
}

// ---------------------------------------------------------------------------
// launch
// ---------------------------------------------------------------------------
extern "C" void kernel_launch(void* const* d_in, const int* in_sizes, int n_in,
                              void* d_out, int out_size)
{
    const float* x     = (const float*)d_in[0];
    const float* m     = (const float*)d_in[1];
    const float* gamma = (const float*)d_in[2];
    const float* beta  = (const float*)d_in[3];
    const float* Wqkv  = (const float*)d_in[4];
    const float* Wout  = (const float*)d_in[5];
    float* out = (float*)d_out;

    float *xn, *qkvp, *ctx;
    cudaGetSymbolAddress((void**)&xn,   g_xn);
    cudaGetSymbolAddress((void**)&qkvp, g_qkv);
    cudaGetSymbolAddress((void**)&ctx,  g_ctx);

    cudaFuncSetAttribute(attn_kernel,
                         cudaFuncAttributeMaxDynamicSharedMemorySize, ATTN_SMEM);

    // 1. LayerNorm
    ln_kernel<<<NROWS, 256>>>(x, gamma, beta, xn);

    // 2. QKV projection: [4096,1024] @ [1024,3072]
    sgemm_kernel<<<dim3(3 * INNER / 128, NROWS / 128), 256>>>(
        xn, Wqkv, qkvp, NROWS, 3 * INNER, DMODEL);

    // 3. masked flash attention
    attn_kernel<<<dim3(NSEQ / 64, HEADS, BATCH), 256, ATTN_SMEM>>>(qkvp, m, ctx);

    // 4. output projection: [4096,1024] @ [1024,1024]
    sgemm_kernel<<<dim3(DMODEL / 128, NROWS / 128), 256>>>(
        ctx, Wout, out, NROWS, DMODEL, DMODEL);
}